// round 2
// baseline (speedup 1.0000x reference)
#include <cuda_runtime.h>
#include <cstddef>

#define VOCAB 50000
#define EMBD  128
#define STORY 200
#define SENT  32
#define BATCH 64
#define QLEN  32
#define HOPS  3

// Scratch (device globals — no allocation allowed)
__device__ float g_emb[4 * BATCH * STORY * EMBD];  // 26.2 MB: emb[k][b][s][e]
__device__ float g_u[BATCH * EMBD];
__device__ float g_lse[BATCH];

// ---------------------------------------------------------------------------
// Kernel 1: embedding gather-sums.
// Rows 0..51199: emb[k][b][s][:] = sum_t A[k][x[b,s,t]][:]
// Rows 51200..51263: u0[b][:] = sum_t A[1][q[b,t]][:]
// 8 rows/block, 32 threads per row (float4 per lane -> 512B coalesced per token row)
// ---------------------------------------------------------------------------
__global__ void embed_kernel(const float* __restrict__ A,
                             const int* __restrict__ x,
                             const int* __restrict__ q) {
    const int NEMB = 4 * BATCH * STORY;  // 51200
    int w    = threadIdx.x >> 5;         // row within block (0..7)
    int lane = threadIdx.x & 31;
    int row  = blockIdx.x * 8 + w;

    __shared__ int toks[8][SENT];

    const int*   tokptr;
    const float* table;
    float*       out;

    if (row < NEMB) {
        int k   = row / (BATCH * STORY);
        int rem = row % (BATCH * STORY);
        tokptr = x + rem * SENT;
        table  = A + (size_t)k * VOCAB * EMBD;
        out    = g_emb + (size_t)row * EMBD;
    } else if (row < NEMB + BATCH) {
        int b  = row - NEMB;
        tokptr = q + b * QLEN;
        table  = A + (size_t)1 * VOCAB * EMBD;
        out    = g_u + b * EMBD;
    } else {
        return;
    }

    toks[w][lane] = tokptr[lane];
    __syncwarp();

    float4 acc = make_float4(0.f, 0.f, 0.f, 0.f);
#pragma unroll 8
    for (int t = 0; t < SENT; t++) {
        const float4* r = (const float4*)(table + (size_t)toks[w][t] * EMBD);
        float4 v = __ldg(&r[lane]);
        acc.x += v.x; acc.y += v.y; acc.z += v.z; acc.w += v.w;
    }
    ((float4*)out)[lane] = acc;
}

// ---------------------------------------------------------------------------
// Kernel 2: 3 attention hops. One block per batch, 256 threads.
// score[s] = dot(emb[k][b][s], u) + TA[s]*sum(u)
// p = softmax(score); u += (sum_s p[s]*emb[k+1][b][s][:]) + dot(TC, p)
// ---------------------------------------------------------------------------
__global__ void hops_kernel(const float* __restrict__ TA,
                            const float* __restrict__ TC) {
    int b   = blockIdx.x;
    int tid = threadIdx.x;
    int warp = tid >> 5, lane = tid & 31;

    __shared__ float su[EMBD];
    __shared__ float sc[STORY];
    __shared__ float wsum[2][EMBD];
    __shared__ float sred[8];
    __shared__ float s_scalar[4];  // sum_u, smax, ssum, tcdot

    if (tid < EMBD) su[tid] = g_u[b * EMBD + tid];
    __syncthreads();

    for (int k = 0; k < HOPS; k++) {
        // sum(u)
        if (tid < EMBD) {
            float v = su[tid];
            for (int o = 16; o > 0; o >>= 1) v += __shfl_down_sync(0xffffffffu, v, o);
            if (lane == 0) sred[warp] = v;
        }
        __syncthreads();
        if (tid == 0) s_scalar[0] = sred[0] + sred[1] + sred[2] + sred[3];
        __syncthreads();
        float sum_u = s_scalar[0];

        // scores: warp per s, lane covers 4 dims via float4
        float4 uv = ((const float4*)su)[lane];
        const float4* embk = (const float4*)(g_emb +
            ((size_t)k * BATCH * STORY + (size_t)b * STORY) * EMBD);
        for (int s = warp; s < STORY; s += 8) {
            float4 m4 = embk[s * 32 + lane];
            float d = m4.x * uv.x + m4.y * uv.y + m4.z * uv.z + m4.w * uv.w;
            for (int o = 16; o > 0; o >>= 1) d += __shfl_down_sync(0xffffffffu, d, o);
            if (lane == 0) sc[s] = d + TA[s] * sum_u;
        }
        __syncthreads();

        // softmax: max
        if (warp == 0) {
            float m = -1e30f;
            for (int s = lane; s < STORY; s += 32) m = fmaxf(m, sc[s]);
            for (int o = 16; o > 0; o >>= 1) m = fmaxf(m, __shfl_down_sync(0xffffffffu, m, o));
            if (lane == 0) s_scalar[1] = m;
        }
        __syncthreads();
        float smax = s_scalar[1];
        if (tid < STORY) sc[tid] = __expf(sc[tid] - smax);
        __syncthreads();
        if (warp == 0) {
            float sm = 0.f, td = 0.f;
            for (int s = lane; s < STORY; s += 32) { sm += sc[s]; td += sc[s] * TC[s]; }
            for (int o = 16; o > 0; o >>= 1) {
                sm += __shfl_down_sync(0xffffffffu, sm, o);
                td += __shfl_down_sync(0xffffffffu, td, o);
            }
            if (lane == 0) { s_scalar[2] = sm; s_scalar[3] = td; }
        }
        __syncthreads();

        // weighted combine with c = emb[k+1]
        int e = tid & 127, part = tid >> 7;
        const float* embc = g_emb +
            ((size_t)(k + 1) * BATCH * STORY + (size_t)b * STORY) * EMBD;
        float acc = 0.f;
        int s0 = part * 100;
#pragma unroll 4
        for (int s = s0; s < s0 + 100; s++) acc += embc[s * EMBD + e] * sc[s];
        wsum[part][e] = acc;
        __syncthreads();
        if (tid < EMBD) {
            float inv = 1.0f / s_scalar[2];
            su[tid] = su[tid] + (wsum[0][tid] + wsum[1][tid] + s_scalar[3]) * inv;
        }
        __syncthreads();
    }
    if (tid < EMBD) g_u[b * EMBD + tid] = su[tid];
}

// ---------------------------------------------------------------------------
// Kernel 3: logits[b][v] = dot(u[b], A[3][v]) using packed fma.rn.f32x2.
// Block = 128 v-tile x 64 batches. 256 threads: (v_local = tid&127, bg = tid>>7).
// Each thread: 1 v, 32 batches packed as 16 f32x2 accumulators.
// ---------------------------------------------------------------------------
__device__ __forceinline__ unsigned long long fma2(unsigned long long a,
                                                   unsigned long long b,
                                                   unsigned long long c) {
    unsigned long long d;
    asm("fma.rn.f32x2 %0, %1, %2, %3;" : "=l"(d) : "l"(a), "l"(b), "l"(c));
    return d;
}
__device__ __forceinline__ unsigned long long pack2(float x) {
    unsigned long long d;
    asm("mov.b64 %0, {%1, %1};" : "=l"(d) : "f"(x));
    return d;
}

__global__ void logits_kernel(const float* __restrict__ A,
                              float* __restrict__ out) {
    const float* A3 = A + (size_t)HOPS * VOCAB * EMBD;

    __shared__ float2 us2[32 * EMBD];   // pair p=(b/2): us2[p*128+e] = (u[2p][e], u[2p+1][e])
    __shared__ float  As[128 * 17];     // 128 v x 16 e chunk, stride-17 pad

    int tid = threadIdx.x;
    // stage u pairs
    for (int i = tid; i < 32 * EMBD; i += 256) {
        int p = i >> 7, e = i & 127;
        us2[i] = make_float2(g_u[(2 * p) * EMBD + e], g_u[(2 * p + 1) * EMBD + e]);
    }

    int vl = tid & 127;
    int bg = tid >> 7;            // 0/1 -> batches [32bg, 32bg+32)
    int v  = blockIdx.x * 128 + vl;
    unsigned long long acc2[16];
#pragma unroll
    for (int j = 0; j < 16; j++) acc2[j] = 0ull;

    const unsigned long long* up =
        (const unsigned long long*)us2 + (size_t)bg * 16 * EMBD;

    for (int c = 0; c < 8; c++) {   // 8 chunks of 16 e
        __syncthreads();
        // load A3 chunk: 512 float4, 2 per thread
#pragma unroll
        for (int i = 0; i < 2; i++) {
            int f   = tid + i * 256;
            int vl2 = f >> 2, e4 = f & 3;
            int vr  = min(blockIdx.x * 128 + vl2, VOCAB - 1);
            float4 val = __ldg((const float4*)A3 + (size_t)vr * 32 + c * 4 + e4);
            float* dst = &As[vl2 * 17 + e4 * 4];
            dst[0] = val.x; dst[1] = val.y; dst[2] = val.z; dst[3] = val.w;
        }
        __syncthreads();

#pragma unroll 4
        for (int e = 0; e < 16; e++) {
            unsigned long long ap = pack2(As[vl * 17 + e]);
            int ue = c * 16 + e;
#pragma unroll
            for (int j = 0; j < 16; j++)
                acc2[j] = fma2(ap, up[j * EMBD + ue], acc2[j]);
        }
    }

    if (v < VOCAB) {
#pragma unroll
        for (int j = 0; j < 16; j++) {
            float lo = __uint_as_float((unsigned)(acc2[j] & 0xffffffffull));
            float hi = __uint_as_float((unsigned)(acc2[j] >> 32));
            out[(size_t)(bg * 32 + 2 * j)     * VOCAB + v] = lo;
            out[(size_t)(bg * 32 + 2 * j + 1) * VOCAB + v] = hi;
        }
    }
}

// ---------------------------------------------------------------------------
// Kernel 4: per-batch log-sum-exp over 50000 logits (online, block per batch)
// ---------------------------------------------------------------------------
__global__ void lse_kernel(const float* __restrict__ out) {
    int b = blockIdx.x, tid = threadIdx.x;
    const float* row = out + (size_t)b * VOCAB;
    float m = -1e30f, s = 0.f;
    for (int v = tid; v < VOCAB; v += 256) {
        float x = row[v];
        if (x > m) { s = s * __expf(m - x) + 1.f; m = x; }
        else       { s += __expf(x - m); }
    }
    for (int o = 16; o > 0; o >>= 1) {
        float m2 = __shfl_down_sync(0xffffffffu, m, o);
        float s2 = __shfl_down_sync(0xffffffffu, s, o);
        float mn = fmaxf(m, m2);
        s = s * __expf(m - mn) + s2 * __expf(m2 - mn);
        m = mn;
    }
    __shared__ float sm[8], ss[8];
    if ((tid & 31) == 0) { sm[tid >> 5] = m; ss[tid >> 5] = s; }
    __syncthreads();
    if (tid == 0) {
        float M = sm[0], S = ss[0];
        for (int w = 1; w < 8; w++) {
            float mn = fmaxf(M, sm[w]);
            S = S * __expf(M - mn) + ss[w] * __expf(sm[w] - mn);
            M = mn;
        }
        g_lse[b] = M + logf(S);
    }
}

// ---------------------------------------------------------------------------
// Kernel 5: out[b][v] -= lse[b]  (float4; 50000 % 4 == 0)
// ---------------------------------------------------------------------------
__global__ void norm_kernel(float* __restrict__ out) {
    int i = blockIdx.x * blockDim.x + threadIdx.x;  // float4 index
    const int N4 = BATCH * VOCAB / 4;               // 800000
    if (i >= N4) return;
    int b = i / (VOCAB / 4);
    float l = g_lse[b];
    float4 v = ((float4*)out)[i];
    v.x -= l; v.y -= l; v.z -= l; v.w -= l;
    ((float4*)out)[i] = v;
}

// ---------------------------------------------------------------------------
extern "C" void kernel_launch(void* const* d_in, const int* in_sizes, int n_in,
                              void* d_out, int out_size) {
    const float* A  = (const float*)d_in[0];  // [4,50000,128]
    const float* TA = (const float*)d_in[1];  // [200]
    const float* TC = (const float*)d_in[2];  // [200]
    const int*   x  = (const int*)d_in[3];    // [64,200,32]
    const int*   q  = (const int*)d_in[4];    // [64,32]
    float* out = (float*)d_out;               // [64,50000]

    embed_kernel<<<6408, 256>>>(A, x, q);     // (51200 + 64) / 8 rows
    hops_kernel<<<64, 256>>>(TA, TC);
    logits_kernel<<<391, 256>>>(A, out);      // ceil(50000/128)
    lse_kernel<<<64, 256>>>(out);
    norm_kernel<<<3125, 256>>>(out);          // 800000 / 256
}

// round 3
// speedup vs baseline: 1.0667x; 1.0667x over previous
#include <cuda_runtime.h>
#include <cstddef>

#define VOCAB 50000
#define EMBD  128
#define STORY 200
#define SENT  32
#define BATCH 64
#define QLEN  32
#define HOPS  3

// Scratch (device globals — no allocation allowed)
__device__ float g_emb[4 * BATCH * STORY * EMBD];  // 26.2 MB: emb[k][b][s][e]
__device__ float g_u[BATCH * EMBD];
__device__ float g_lse[BATCH];
__device__ float g_pm[BATCH * 8];   // lse partial max
__device__ float g_ps[BATCH * 8];   // lse partial sum

// ---------------------------------------------------------------------------
// Kernel 1: embedding gather-sums (L2-roofline bound; unchanged).
// ---------------------------------------------------------------------------
__global__ void embed_kernel(const float* __restrict__ A,
                             const int* __restrict__ x,
                             const int* __restrict__ q) {
    const int NEMB = 4 * BATCH * STORY;  // 51200
    int w    = threadIdx.x >> 5;
    int lane = threadIdx.x & 31;
    int row  = blockIdx.x * 8 + w;

    __shared__ int toks[8][SENT];

    const int*   tokptr;
    const float* table;
    float*       out;

    if (row < NEMB) {
        int k   = row / (BATCH * STORY);
        int rem = row % (BATCH * STORY);
        tokptr = x + rem * SENT;
        table  = A + (size_t)k * VOCAB * EMBD;
        out    = g_emb + (size_t)row * EMBD;
    } else if (row < NEMB + BATCH) {
        int b  = row - NEMB;
        tokptr = q + b * QLEN;
        table  = A + (size_t)1 * VOCAB * EMBD;
        out    = g_u + b * EMBD;
    } else {
        return;
    }

    toks[w][lane] = tokptr[lane];
    __syncwarp();

    float4 acc = make_float4(0.f, 0.f, 0.f, 0.f);
#pragma unroll 8
    for (int t = 0; t < SENT; t++) {
        const float4* r = (const float4*)(table + (size_t)toks[w][t] * EMBD);
        float4 v = __ldg(&r[lane]);
        acc.x += v.x; acc.y += v.y; acc.z += v.z; acc.w += v.w;
    }
    ((float4*)out)[lane] = acc;
}

// ---------------------------------------------------------------------------
// Kernel 2: 3 attention hops (unchanged).
// ---------------------------------------------------------------------------
__global__ void hops_kernel(const float* __restrict__ TA,
                            const float* __restrict__ TC) {
    int b   = blockIdx.x;
    int tid = threadIdx.x;
    int warp = tid >> 5, lane = tid & 31;

    __shared__ float su[EMBD];
    __shared__ float sc[STORY];
    __shared__ float wsum[2][EMBD];
    __shared__ float sred[8];
    __shared__ float s_scalar[4];

    if (tid < EMBD) su[tid] = g_u[b * EMBD + tid];
    __syncthreads();

    for (int k = 0; k < HOPS; k++) {
        if (tid < EMBD) {
            float v = su[tid];
            for (int o = 16; o > 0; o >>= 1) v += __shfl_down_sync(0xffffffffu, v, o);
            if (lane == 0) sred[warp] = v;
        }
        __syncthreads();
        if (tid == 0) s_scalar[0] = sred[0] + sred[1] + sred[2] + sred[3];
        __syncthreads();
        float sum_u = s_scalar[0];

        float4 uv = ((const float4*)su)[lane];
        const float4* embk = (const float4*)(g_emb +
            ((size_t)k * BATCH * STORY + (size_t)b * STORY) * EMBD);
        for (int s = warp; s < STORY; s += 8) {
            float4 m4 = embk[s * 32 + lane];
            float d = m4.x * uv.x + m4.y * uv.y + m4.z * uv.z + m4.w * uv.w;
            for (int o = 16; o > 0; o >>= 1) d += __shfl_down_sync(0xffffffffu, d, o);
            if (lane == 0) sc[s] = d + TA[s] * sum_u;
        }
        __syncthreads();

        if (warp == 0) {
            float m = -1e30f;
            for (int s = lane; s < STORY; s += 32) m = fmaxf(m, sc[s]);
            for (int o = 16; o > 0; o >>= 1) m = fmaxf(m, __shfl_down_sync(0xffffffffu, m, o));
            if (lane == 0) s_scalar[1] = m;
        }
        __syncthreads();
        float smax = s_scalar[1];
        if (tid < STORY) sc[tid] = __expf(sc[tid] - smax);
        __syncthreads();
        if (warp == 0) {
            float sm = 0.f, td = 0.f;
            for (int s = lane; s < STORY; s += 32) { sm += sc[s]; td += sc[s] * TC[s]; }
            for (int o = 16; o > 0; o >>= 1) {
                sm += __shfl_down_sync(0xffffffffu, sm, o);
                td += __shfl_down_sync(0xffffffffu, td, o);
            }
            if (lane == 0) { s_scalar[2] = sm; s_scalar[3] = td; }
        }
        __syncthreads();

        int e = tid & 127, part = tid >> 7;
        const float* embc = g_emb +
            ((size_t)(k + 1) * BATCH * STORY + (size_t)b * STORY) * EMBD;
        float acc = 0.f;
        int s0 = part * 100;
#pragma unroll 4
        for (int s = s0; s < s0 + 100; s++) acc += embc[s * EMBD + e] * sc[s];
        wsum[part][e] = acc;
        __syncthreads();
        if (tid < EMBD) {
            float inv = 1.0f / s_scalar[2];
            su[tid] = su[tid] + (wsum[0][tid] + wsum[1][tid] + s_scalar[3]) * inv;
        }
        __syncthreads();
    }
    if (tid < EMBD) g_u[b * EMBD + tid] = su[tid];
}

// ---------------------------------------------------------------------------
// Kernel 3: logits via packed fma.rn.f32x2, broadcast-u restructure.
// Block = 256 v (2 per thread) x 64 batches. 256 threads:
//   vp = tid&127 -> vocab rows v0=2vp, v1=2vp+1 of the block's 256-v tile
//   bg = tid>>7  -> batch-pair group (16 pairs = 32 batches)
// u loads are warp-uniform broadcasts (8B crossbar each); A values register-
// resident per e. 51 issue slots per 32 fma2 -> ~78% fma-pipe utilization.
// ---------------------------------------------------------------------------
__device__ __forceinline__ unsigned long long fma2(unsigned long long a,
                                                   unsigned long long b,
                                                   unsigned long long c) {
    unsigned long long d;
    asm("fma.rn.f32x2 %0, %1, %2, %3;" : "=l"(d) : "l"(a), "l"(b), "l"(c));
    return d;
}
__device__ __forceinline__ unsigned long long pack2(float x) {
    unsigned long long d;
    asm("mov.b64 %0, {%1, %1};" : "=l"(d) : "f"(x));
    return d;
}
__device__ __forceinline__ float lo32(unsigned long long a) {
    return __uint_as_float((unsigned)(a & 0xffffffffull));
}
__device__ __forceinline__ float hi32(unsigned long long a) {
    return __uint_as_float((unsigned)(a >> 32));
}

__global__ void __launch_bounds__(256) logits_kernel(const float* __restrict__ A,
                                                     float* __restrict__ out) {
    const float* A3 = A + (size_t)HOPS * VOCAB * EMBD;

    __shared__ float2 up2[32 * EMBD];   // 32 KB: pair p -> (u[2p][e], u[2p+1][e])
    __shared__ float  As[8 * 256];      // 8 KB: chunk, layout [e][v]

    int tid = threadIdx.x;
    for (int i = tid; i < 32 * EMBD; i += 256) {
        int p = i >> 7, e = i & 127;
        up2[p * EMBD + e] = make_float2(g_u[(2 * p) * EMBD + e],
                                        g_u[(2 * p + 1) * EMBD + e]);
    }

    int vp = tid & 127;
    int bg = tid >> 7;
    int vbase = blockIdx.x * 256;

    unsigned long long acc0[16], acc1[16];
#pragma unroll
    for (int j = 0; j < 16; j++) { acc0[j] = 0ull; acc1[j] = 0ull; }

    const unsigned long long* uq =
        (const unsigned long long*)up2 + (size_t)bg * 16 * EMBD;

    for (int c = 0; c < 16; c++) {   // 16 chunks of 8 e
        __syncthreads();
        // load A3 chunk [256 v x 8 e] -> As[e][v]; 512 float4, 2 per thread
#pragma unroll
        for (int i = 0; i < 2; i++) {
            int f   = tid + i * 256;        // 0..511
            int vl2 = f >> 1;               // 0..255
            int e4  = f & 1;                // which float4 of the 8-e chunk
            int vr  = min(vbase + vl2, VOCAB - 1);
            float4 val = __ldg((const float4*)A3 + (size_t)vr * 32 + c * 2 + e4);
            int eb = e4 * 4;
            As[(eb + 0) * 256 + vl2] = val.x;
            As[(eb + 1) * 256 + vl2] = val.y;
            As[(eb + 2) * 256 + vl2] = val.z;
            As[(eb + 3) * 256 + vl2] = val.w;
        }
        __syncthreads();

#pragma unroll
        for (int e = 0; e < 8; e++) {
            float2 a01 = ((const float2*)(As + e * 256))[vp];
            unsigned long long a0 = pack2(a01.x);
            unsigned long long a1 = pack2(a01.y);
            int ue = c * 8 + e;
#pragma unroll
            for (int j = 0; j < 16; j++) {
                unsigned long long uu = uq[j * EMBD + ue];  // warp-uniform broadcast
                acc0[j] = fma2(a0, uu, acc0[j]);
                acc1[j] = fma2(a1, uu, acc1[j]);
            }
        }
    }

    int v0 = vbase + 2 * vp;
    if (v0 < VOCAB) {
#pragma unroll
        for (int j = 0; j < 16; j++) {
            int b = bg * 32 + 2 * j;
            float2 r0 = make_float2(lo32(acc0[j]), lo32(acc1[j]));
            float2 r1 = make_float2(hi32(acc0[j]), hi32(acc1[j]));
            *(float2*)(out + (size_t)b * VOCAB + v0)       = r0;
            *(float2*)(out + (size_t)(b + 1) * VOCAB + v0) = r1;
        }
    }
}

// ---------------------------------------------------------------------------
// Kernel 4a: split-K log-sum-exp partials. grid (64 batches, 8 segments).
// ---------------------------------------------------------------------------
__global__ void lse_part_kernel(const float* __restrict__ out) {
    int b = blockIdx.x, seg = blockIdx.y, tid = threadIdx.x;
    const int SEG = VOCAB / 8;  // 6250
    const float* row = out + (size_t)b * VOCAB + seg * SEG;

    float m = -1e30f, s = 0.f;
    for (int v = tid; v < SEG; v += 256) {
        float x = row[v];
        if (x > m) { s = s * __expf(m - x) + 1.f; m = x; }
        else       { s += __expf(x - m); }
    }
    for (int o = 16; o > 0; o >>= 1) {
        float m2 = __shfl_down_sync(0xffffffffu, m, o);
        float s2 = __shfl_down_sync(0xffffffffu, s, o);
        float mn = fmaxf(m, m2);
        s = s * __expf(m - mn) + s2 * __expf(m2 - mn);
        m = mn;
    }
    __shared__ float sm[8], ss[8];
    if ((tid & 31) == 0) { sm[tid >> 5] = m; ss[tid >> 5] = s; }
    __syncthreads();
    if (tid == 0) {
        float M = sm[0], S = ss[0];
        for (int w = 1; w < 8; w++) {
            float mn = fmaxf(M, sm[w]);
            S = S * __expf(M - mn) + ss[w] * __expf(sm[w] - mn);
            M = mn;
        }
        g_pm[b * 8 + seg] = M;
        g_ps[b * 8 + seg] = S;
    }
}

// ---------------------------------------------------------------------------
// Kernel 4b: combine 8 partials per batch -> g_lse. 1 block, 64 threads.
// ---------------------------------------------------------------------------
__global__ void lse_combine_kernel() {
    int b = threadIdx.x;
    float M = g_pm[b * 8], S = g_ps[b * 8];
#pragma unroll
    for (int w = 1; w < 8; w++) {
        float m2 = g_pm[b * 8 + w], s2 = g_ps[b * 8 + w];
        float mn = fmaxf(M, m2);
        S = S * __expf(M - mn) + s2 * __expf(m2 - mn);
        M = mn;
    }
    g_lse[b] = M + logf(S);
}

// ---------------------------------------------------------------------------
// Kernel 5: out[b][v] -= lse[b]  (float4)
// ---------------------------------------------------------------------------
__global__ void norm_kernel(float* __restrict__ out) {
    int i = blockIdx.x * blockDim.x + threadIdx.x;
    const int N4 = BATCH * VOCAB / 4;
    if (i >= N4) return;
    int b = i / (VOCAB / 4);
    float l = g_lse[b];
    float4 v = ((float4*)out)[i];
    v.x -= l; v.y -= l; v.z -= l; v.w -= l;
    ((float4*)out)[i] = v;
}

// ---------------------------------------------------------------------------
extern "C" void kernel_launch(void* const* d_in, const int* in_sizes, int n_in,
                              void* d_out, int out_size) {
    const float* A  = (const float*)d_in[0];
    const float* TA = (const float*)d_in[1];
    const float* TC = (const float*)d_in[2];
    const int*   x  = (const int*)d_in[3];
    const int*   q  = (const int*)d_in[4];
    float* out = (float*)d_out;

    embed_kernel<<<6408, 256>>>(A, x, q);
    hops_kernel<<<64, 256>>>(TA, TC);
    logits_kernel<<<196, 256>>>(A, out);      // ceil(50000/256)
    lse_part_kernel<<<dim3(64, 8), 256>>>(out);
    lse_combine_kernel<<<1, 64>>>();
    norm_kernel<<<3125, 256>>>(out);
}